// round 16
// baseline (speedup 1.0000x reference)
#include <cuda_runtime.h>

typedef unsigned long long ull;

#define HH 256
#define WW 256
#define PP 512
#define NPIX (HH * WW)
#define NB_T1 256          // term1: one block per row (long blocks, go first)
#define NB_T2 2048         // term2: eighth-row blocks (8 per row)
#define NBLK (NB_T1 + NB_T2)
#define QW 32              // pixels per term2 block

// Scratch (device globals — zero-initialized at load; finalize re-zeroes them
// so every graph replay starts clean).
__device__ float g_sums8[8][PP];   // per-eighth partial sums of wd^-5
__device__ float g_term1;
__device__ float g_sumabs;
__device__ unsigned g_count;

// ---- packed f32x2 helpers ----
__device__ __forceinline__ ull pack2(float lo, float hi) {
    ull r; asm("mov.b64 %0, {%1, %2};" : "=l"(r) : "f"(lo), "f"(hi)); return r;
}
__device__ __forceinline__ void unpack2(ull v, float& lo, float& hi) {
    asm("mov.b64 {%0, %1}, %2;" : "=f"(lo), "=f"(hi) : "l"(v));
}
__device__ __forceinline__ ull add2(ull a, ull b) {
    ull d; asm("add.rn.f32x2 %0, %1, %2;" : "=l"(d) : "l"(a), "l"(b)); return d;
}
__device__ __forceinline__ ull mul2(ull a, ull b) {
    ull d; asm("mul.rn.f32x2 %0, %1, %2;" : "=l"(d) : "l"(a), "l"(b)); return d;
}
__device__ __forceinline__ ull fma2(ull a, ull b, ull c) {
    ull d; asm("fma.rn.f32x2 %0, %1, %2, %3;" : "=l"(d) : "l"(a), "l"(b), "l"(c)); return d;
}
__device__ __forceinline__ float fsqrt_approx(float x) {
    float y; asm("sqrt.approx.f32 %0, %1;" : "=f"(y) : "f"(x)); return y;
}
__device__ __forceinline__ float frcp_approx(float x) {
    float y; asm("rcp.approx.f32 %0, %1;" : "=f"(y) : "f"(x)); return y;
}

// ---------------------------------------------------------------------------
// One fused kernel, 2304 blocks:
//   [0, 256):     term1 — row b, per-pixel min over P via single-FFMA form
//                 min(d2 - fw^2) with s=-2px, u=px^2+dy^2
//   [256, 2304):  term2 — unit u=b-256: row u>>3, pixel eighth (u&7)*32,
//                 512 points (2/thread); 2 pixels/iter, 2-way paired rcp,
//                 fully unrolled 16-iteration loop
//   last block:   finalize + re-zero (self-cleaning for graph replays)
// ---------------------------------------------------------------------------
__global__ void __launch_bounds__(256, 8)
whd_fused(const float* __restrict__ heat,
          const float* __restrict__ pts,
          float* __restrict__ out) {
    __shared__ __align__(16) unsigned char sraw[4096];
    __shared__ float swred[16];
    __shared__ float s_scal;
    __shared__ int s_last;

    const int t = threadIdx.x;
    const int b = blockIdx.x;
    const int lane = t & 31;
    const int wid = t >> 5;
    const unsigned FULL = 0xFFFFFFFFu;

    if (b >= NB_T1) {
        // ================= term2: eighth-row =================
        const int u = b - NB_T1;
        const int row = u >> 3;
        const int qi = u & 7;
        const int wstart = qi << 5;
        float4 pv = ((const float4*)pts)[t];   // points 2t, 2t+1

        // block maxd: max lattice distance = max corner distance (exact)
        const float C = 255.0f;
        float mdy0 = fmaxf(pv.x, fabsf(C - pv.x));
        float mdx0 = fmaxf(pv.y, fabsf(C - pv.y));
        float mdy1 = fmaxf(pv.z, fabsf(C - pv.z));
        float mdx1 = fmaxf(pv.w, fabsf(C - pv.w));
        float m2 = fmaxf(fmaf(mdy0, mdy0, mdx0 * mdx0),
                         fmaf(mdy1, mdy1, mdx1 * mdx1));
        #pragma unroll
        for (int off = 16; off > 0; off >>= 1)
            m2 = fmaxf(m2, __shfl_xor_sync(FULL, m2, off));
        if (lane == 0) swred[wid] = m2;
        __syncthreads();
        if (t == 0) {
            float mm = swred[0];
            #pragma unroll
            for (int i = 1; i < 8; i++) mm = fmaxf(mm, swred[i]);
            s_scal = sqrtf(mm);
        }
        __syncthreads();
        const float maxd = s_scal;

        // stage 32 pixels interleaved (hm, cpix); read back as float4 pairs
        float2* shc2 = (float2*)sraw;     // 32 * 8B
        if (t < QW) {
            float hm = heat[row * WW + wstart + t];
            shc2[t] = make_float2(hm, fmaf(-hm, maxd, maxd));
        }
        __syncthreads();
        const float4* shc4 = (const float4*)sraw;  // [16]: (hm0,cp0,hm1,cp1)

        const float fh = (float)row;
        float dy0 = fh - pv.x, dy1 = fh - pv.z;
        ull dy2p = pack2(dy0 * dy0, dy1 * dy1);
        ull dxp  = pack2((float)wstart - pv.y, (float)wstart - pv.w);
        ull accp = pack2(0.0f, 0.0f);
        const ull onep = pack2(1.0f, 1.0f);

        #pragma unroll
        for (int k = 0; k < QW / 2; k++) {
            float4 hc = shc4[k];                // LDS.128: 2 pixels (hm,cp)
            // pixel 0 distances (packed over 2 points)
            ull d2p0 = fma2(dxp, dxp, dy2p);
            dxp = add2(dxp, onep);
            // pixel 1 distances
            ull d2p1 = fma2(dxp, dxp, dy2p);
            dxp = add2(dxp, onep);
            float d2a0, d2b0, d2a1, d2b1;
            unpack2(d2p0, d2a0, d2b0);
            unpack2(d2p1, d2a1, d2b1);
            float sa0 = fsqrt_approx(d2a0);     // 4 independent MUFU sqrt
            float sb0 = fsqrt_approx(d2b0);
            float sa1 = fsqrt_approx(d2a1);
            float sb1 = fsqrt_approx(d2b1);
            float wa0 = fmaf(hc.x, sa0, hc.y);  // wd = hm*dist + cpix
            float wb0 = fmaf(hc.x, sb0, hc.y);
            float wa1 = fmaf(hc.z, sa1, hc.w);
            float wb1 = fmaf(hc.z, sb1, hc.w);
            // 2-way paired reciprocal per pixel (1 MUFU per 2 points)
            float p0  = wa0 * wb0;
            float p1  = wa1 * wb1;
            float ip0 = frcp_approx(p0);
            float ip1 = frcp_approx(p1);
            float ra0 = ip0 * wb0, rb0 = ip0 * wa0;
            float ra1 = ip1 * wb1, rb1 = ip1 * wa1;
            // wd^-5 accumulate, packed per pixel
            ull rp0 = pack2(ra0, rb0);
            ull rp1 = pack2(ra1, rb1);
            ull r20 = mul2(rp0, rp0);
            ull r21 = mul2(rp1, rp1);
            ull r40 = mul2(r20, r20);
            ull r41 = mul2(r21, r21);
            accp = fma2(r40, rp0, accp);
            accp = fma2(r41, rp1, accp);
        }
        float a0, a1; unpack2(accp, a0, a1);
        atomicAdd(&g_sums8[qi][2 * t + 0], a0);
        atomicAdd(&g_sums8[qi][2 * t + 1], a1);
    } else {
        // ================= term1: row = b =================
        // track min over points of (d2 - fw^2) = fma(-2*px, fw, px^2+dy^2)
        const int row = b;
        float4* pc4 = (float4*)sraw;      // 256 * 16B: (s0,u0,s1,u1)
        const float fh = (float)row;
        {
            float4 pw = ((const float4*)pts)[t];   // (py0,px0,py1,px1)
            float dy0 = fh - pw.x, dy1 = fh - pw.z;
            pc4[t] = make_float4(-2.0f * pw.y, fmaf(pw.y, pw.y, dy0 * dy0),
                                 -2.0f * pw.w, fmaf(pw.w, pw.w, dy1 * dy1));
        }
        __syncthreads();

        const float fw = (float)t;
        float m0 = 3.4e38f, m1 = 3.4e38f, m2v = 3.4e38f, m3 = 3.4e38f;
        #pragma unroll 8
        for (int i = 0; i < PP / 2; i += 2) {
            float4 v0 = pc4[i], v1 = pc4[i + 1];
            m0  = fminf(m0,  fmaf(v0.x, fw, v0.y));
            m1  = fminf(m1,  fmaf(v0.z, fw, v0.w));
            m2v = fminf(m2v, fmaf(v1.x, fw, v1.y));
            m3  = fminf(m3,  fmaf(v1.z, fw, v1.w));
        }
        float m = fminf(fminf(m0, m1), fminf(m2v, m3)) + fw * fw;

        float hm  = heat[row * WW + t];
        float val = hm * sqrtf(m);
        float av  = fabsf(hm);
        #pragma unroll
        for (int off = 16; off > 0; off >>= 1) {
            val += __shfl_down_sync(FULL, val, off);
            av  += __shfl_down_sync(FULL, av,  off);
        }
        if (lane == 0) { swred[wid] = val; swred[8 + wid] = av; }
        __syncthreads();
        if (wid == 0) {
            float v = (lane < 8) ? swred[lane] : 0.0f;
            float a = (lane < 8) ? swred[8 + lane] : 0.0f;
            #pragma unroll
            for (int off = 4; off > 0; off >>= 1) {
                v += __shfl_down_sync(FULL, v, off);
                a += __shfl_down_sync(FULL, a, off);
            }
            if (lane == 0) {
                atomicAdd(&g_term1,  v);
                atomicAdd(&g_sumabs, a);
            }
        }
    }

    // ================= last-block finalize =================
    __threadfence();
    __syncthreads();
    if (t == 0)
        s_last = (atomicAdd(&g_count, 1u) == (unsigned)(NBLK - 1));
    __syncthreads();

    if (s_last) {
        float local = 0.0f;
        #pragma unroll
        for (int k = 0; k < 2; k++) {
            int p = t + k * 256;
            float s = 0.0f;
            #pragma unroll
            for (int q = 0; q < 8; q++) {
                s += __ldcg(&g_sums8[q][p]);
                g_sums8[q][p] = 0.0f;
            }
            float mv = s * (1.0f / (float)NPIX);
            local += exp2f(-0.2f * __log2f(mv));   // mv^(-0.2)
        }
        #pragma unroll
        for (int off = 16; off > 0; off >>= 1)
            local += __shfl_down_sync(FULL, local, off);
        if (lane == 0) swred[wid] = local;
        __syncthreads();
        if (t == 0) {
            float tot = 0.0f;
            #pragma unroll
            for (int i = 0; i < 8; i++) tot += swred[i];
            float t1 = __ldcg(&g_term1);
            float sa = __ldcg(&g_sumabs);
            out[0] = t1 / sa + tot * (1.0f / (float)PP);
            g_term1  = 0.0f;
            g_sumabs = 0.0f;
            g_count  = 0u;
        }
    }
}

// ---------------------------------------------------------------------------
extern "C" void kernel_launch(void* const* d_in, const int* in_sizes, int n_in,
                              void* d_out, int out_size) {
    const float* heat = (const float*)d_in[0];
    const float* pts  = (const float*)d_in[1];
    float* out = (float*)d_out;

    whd_fused<<<NBLK, 256>>>(heat, pts, out);
}